// round 15
// baseline (speedup 1.0000x reference)
#include <cuda_runtime.h>
#include <cstdint>
#include <math.h>

// ---------------- scratch (device globals; no allocation) ----------------
__device__ float g_k1  [16 * 512 * 200];   // key conv1 partial (ci 0-127, +bias)
__device__ float g_k1b [16 * 512 * 200];   // key conv1 partial (ci 128-255)
__device__ float g_k   [16 *  80 * 200];   // key encoder out
__device__ float g_q1  [16 * 160 * 800];   // query conv1 out
__device__ float g_qf  [16 *  80 * 800];   // query encoder out
__device__ float g_kw1T[768 * 512];        // kw1 transposed [(ci*3+k)][co]
__device__ float g_qw1T[240 * 160];
__device__ float g_kw2T[512 *  80];        // kw2 transposed [ci][co]
__device__ float g_qw2T[160 *  80];
__device__ float g_qw3T[ 80 *  80];

// ---------------- packed fp32x2 FMA (Blackwell) ---------------------------
__device__ __forceinline__ float2 ffma2(float2 a, float2 b, float2 c) {
    unsigned long long ua = *reinterpret_cast<unsigned long long*>(&a);
    unsigned long long ub = *reinterpret_cast<unsigned long long*>(&b);
    unsigned long long uc = *reinterpret_cast<unsigned long long*>(&c);
    unsigned long long ud;
    asm("fma.rn.f32x2 %0, %1, %2, %3;" : "=l"(ud) : "l"(ua), "l"(ub), "l"(uc));
    return *reinterpret_cast<float2*>(&ud);
}
__device__ __forceinline__ float2 dup(float v) { return make_float2(v, v); }

// ---------------- cp.async helpers ----------------------------------------
__device__ __forceinline__ void cp_async4(void* dst, const void* src, bool pred) {
    unsigned int d = (unsigned int)__cvta_generic_to_shared(dst);
    int sz = pred ? 4 : 0;
    asm volatile("cp.async.ca.shared.global [%0], [%1], 4, %2;"
                 :: "r"(d), "l"(src), "r"(sz) : "memory");
}
__device__ __forceinline__ void cp_async16(void* dst, const void* src) {
    unsigned int d = (unsigned int)__cvta_generic_to_shared(dst);
    asm volatile("cp.async.ca.shared.global [%0], [%1], 16;"
                 :: "r"(d), "l"(src) : "memory");
}
#define CP_COMMIT() asm volatile("cp.async.commit_group;" ::: "memory")
#define CP_WAIT0()  asm volatile("cp.async.wait_group 0;" ::: "memory")

// =================== PREP: tiled (coalesced) weight transposes ============
__global__ void prep_kernel(const float* __restrict__ kw1, const float* __restrict__ qw1,
                            const float* __restrict__ kw2, const float* __restrict__ qw2,
                            const float* __restrict__ qw3,
                            float* __restrict__ kw1T, float* __restrict__ qw1T,
                            float* __restrict__ kw2T, float* __restrict__ qw2T,
                            float* __restrict__ qw3T)
{
    __shared__ float tile[32][33];
    int id = blockIdx.x;
    const float* src; float* dst; int R, C, bi, bj;
    if (id < 384)            { src = kw1; dst = kw1T; R = 512; C = 768; bi = id / 24; bj = id % 24; }
    else if ((id -= 384) < 40) { src = qw1; dst = qw1T; R = 160; C = 240; bi = id / 8;  bj = id % 8;  }
    else if ((id -= 40) < 48)  { src = kw2; dst = kw2T; R = 80;  C = 512; bi = id / 16; bj = id % 16; }
    else if ((id -= 48) < 15)  { src = qw2; dst = qw2T; R = 80;  C = 160; bi = id / 5;  bj = id % 5;  }
    else      { id -= 15;        src = qw3; dst = qw3T; R = 80;  C = 80;  bi = id / 3;  bj = id % 3;  }

    const int r0 = bi * 32, c0 = bj * 32;
    const int tx = threadIdx.x & 31, ty = threadIdx.x >> 5;

    #pragma unroll
    for (int yy = ty; yy < 32; yy += 8) {
        int r = r0 + yy, c = c0 + tx;
        tile[yy][tx] = (r < R && c < C) ? src[(size_t)r * C + c] : 0.f;
    }
    __syncthreads();
    #pragma unroll
    for (int yy = ty; yy < 32; yy += 8) {
        int c = c0 + yy, r = r0 + tx;
        if (c < C && r < R) dst[(size_t)c * R + r] = tile[tx][yy];
    }
}

// =================== STAGE A: conv3 with cp.async double buffering ========
// MODE 0: y = relu(acc + bias); MODE 1: y = acc + bias; MODE 2: y = acc.
template<int CINFULL, int CINPART, int COUT, int TLEN, int CPAIRS, int CICH, int MODE>
__device__ __forceinline__ void conv3_body(
    const float* __restrict__ x, const float* __restrict__ wT,
    const float* __restrict__ bias, float* __restrict__ y,
    int b, int t_tile, int co_tile, int ci_base, float* smem)
{
    constexpr int COT = 32 * CPAIRS;
    constexpr int NW4 = CICH * 3 * COT / 4;
    constexpr int BUF = CICH * 68 + CICH * 3 * COT;
    constexpr int NCH = CINPART / CICH;

    const int tid = threadIdx.x;
    const int cg = tid & 15, tg = tid >> 4;
    const int tt = tg * 4, ct = cg * 2 * CPAIRS;
    const int t0 = t_tile * 64, co0 = co_tile * COT;
    const bool active = (t0 + tt) < TLEN;

    auto stage = [&](int ch, int buf) {
        float* sx = smem + buf * BUF;
        float* sw = sx + CICH * 68;
        const int ci0 = ci_base + ch * CICH;
        for (int idx = tid; idx < CICH * 66; idx += 256) {
            int cc = idx / 66, j = idx - cc * 66;
            int t = t0 + j - 1;
            bool p = (t >= 0 && t < TLEN);
            cp_async4(&sx[cc * 68 + j],
                      &x[((size_t)(b * CINFULL) + ci0 + cc) * TLEN + t], p);
        }
        for (int idx = tid; idx < NW4; idx += 256) {
            int r = idx / (COT / 4), c4 = idx - r * (COT / 4);
            cp_async16(&sw[r * COT + c4 * 4],
                       &wT[(size_t)(ci0 * 3 + r) * COUT + co0 + c4 * 4]);
        }
        CP_COMMIT();
    };

    float2 acc[CPAIRS][4] = {};

    stage(0, 0);
    for (int ch = 0; ch < NCH; ch++) {
        const int buf = ch & 1;
        CP_WAIT0();
        __syncthreads();
        if (ch + 1 < NCH) stage(ch + 1, buf ^ 1);

        if (active) {
            const float* sx = smem + buf * BUF;
            const float* sw = sx + CICH * 68;
            #pragma unroll
            for (int cc = 0; cc < CICH; cc++) {
                const float* xr = &sx[cc * 68 + tt];
                float4 xa = *(const float4*)xr;
                float2 xb = *(const float2*)(xr + 4);
                float2 xv[6] = { dup(xa.x), dup(xa.y), dup(xa.z),
                                 dup(xa.w), dup(xb.x), dup(xb.y) };
                float2 wk[3][CPAIRS];
                #pragma unroll
                for (int k = 0; k < 3; k++) {
                    const float* wb = &sw[(cc * 3 + k) * COT + ct];
                    if constexpr ((CPAIRS & 1) == 0) {
                        #pragma unroll
                        for (int q = 0; q < CPAIRS / 2; q++) {
                            float4 wv = *(const float4*)(wb + 4 * q);
                            wk[k][2*q]   = make_float2(wv.x, wv.y);
                            wk[k][2*q+1] = make_float2(wv.z, wv.w);
                        }
                    } else {
                        #pragma unroll
                        for (int p = 0; p < CPAIRS; p++)
                            wk[k][p] = *(const float2*)(wb + 2 * p);
                    }
                }
                #pragma unroll
                for (int u = 0; u < 4; u++)
                    #pragma unroll
                    for (int p = 0; p < CPAIRS; p++)
                        acc[p][u] = ffma2(wk[0][p], xv[u],
                                    ffma2(wk[1][p], xv[u+1],
                                    ffma2(wk[2][p], xv[u+2], acc[p][u])));
            }
        }
        __syncthreads();
    }

    if (active) {
        #pragma unroll
        for (int p = 0; p < CPAIRS; p++) {
            int co = co0 + ct + 2 * p;
            float2 bv = (MODE == 2) ? make_float2(0.f, 0.f)
                                    : *(const float2*)&bias[co];
            float4 v0, v1;
            if constexpr (MODE == 0) {
                v0 = { fmaxf(acc[p][0].x + bv.x, 0.f), fmaxf(acc[p][1].x + bv.x, 0.f),
                       fmaxf(acc[p][2].x + bv.x, 0.f), fmaxf(acc[p][3].x + bv.x, 0.f) };
                v1 = { fmaxf(acc[p][0].y + bv.y, 0.f), fmaxf(acc[p][1].y + bv.y, 0.f),
                       fmaxf(acc[p][2].y + bv.y, 0.f), fmaxf(acc[p][3].y + bv.y, 0.f) };
            } else {
                v0 = { acc[p][0].x + bv.x, acc[p][1].x + bv.x,
                       acc[p][2].x + bv.x, acc[p][3].x + bv.x };
                v1 = { acc[p][0].y + bv.y, acc[p][1].y + bv.y,
                       acc[p][2].y + bv.y, acc[p][3].y + bv.y };
            }
            *(float4*)&y[((size_t)(b * COUT) + co    ) * TLEN + t0 + tt] = v0;
            *(float4*)&y[((size_t)(b * COUT) + co + 1) * TLEN + t0 + tt] = v1;
        }
    }
}

__global__ void __launch_bounds__(256)
stageA_kernel(
    const float* __restrict__ keys, const float* __restrict__ kb1,
    const float* __restrict__ queries, const float* __restrict__ qb1,
    float* __restrict__ k1out, float* __restrict__ k1outb, float* __restrict__ q1out)
{
    extern __shared__ float smem[];
    int id = blockIdx.x;
    if (id < 1024) {                     // key: 2 CIN-halves x 16 b x 8 co x 4 t
        int half = id >> 9, rem = id & 511;
        int b = rem >> 5, r = rem & 31;
        if (half == 0)
            conv3_body<256, 128, 512, 200, 2, 16, 1>(keys, g_kw1T, kb1, k1out,
                                                     b, r & 3, r >> 2, 0, smem);
        else
            conv3_body<256, 128, 512, 200, 2, 16, 2>(keys, g_kw1T, kb1, k1outb,
                                                     b, r & 3, r >> 2, 128, smem);
    } else {                             // query: CICH=8
        int j = id - 1024;
        conv3_body<80, 80, 160, 800, 5, 8, 0>(queries, g_qw1T, qb1, q1out,
                                              j / 13, j % 13, 0, 0, smem);
    }
}

// =================== STAGE B: key 1x1 (fused relu(a+b), piped) + qchain ===
// key 1x1: stages both partial buffers, computes relu(a+b) in the inner loop.
// BUF = 2048 + 2048 + 2560 = 6656 fl; double buffered = 53248 B.
__device__ __forceinline__ void key1x1_body(
    const float* __restrict__ xa, const float* __restrict__ xb,
    const float* __restrict__ wT, const float* __restrict__ bias,
    float* __restrict__ y, int b, int t_tile, float* smem)
{
    constexpr int BUF = 6656;
    const int tid = threadIdx.x;
    const int cg = tid & 7, tg = tid >> 3;
    const int tt = tg * 2, cb = cg * 10;
    const int t0 = t_tile * 64;
    const bool active = (t0 + tt) < 200;
    float2 acc[5][2] = {};

    auto stage = [&](int ch, int buf) {
        float* sxa = smem + buf * BUF;
        float* sxb = sxa + 2048;
        float* sw  = sxb + 2048;
        const int ci0 = ch * 32;
        for (int idx = tid; idx < 2048; idx += 256) {
            int cc = idx >> 6, j = idx & 63;
            int t = t0 + j;
            size_t gi = ((size_t)(b * 512) + ci0 + cc) * 200 + t;
            bool p = t < 200;
            cp_async4(&sxa[idx], &xa[gi], p);
            cp_async4(&sxb[idx], &xb[gi], p);
        }
        for (int idx = tid; idx < 640; idx += 256) {
            int r = idx / 20, c4 = idx - r * 20;
            cp_async16(&sw[r * 80 + c4 * 4],
                       &wT[(size_t)(ci0 + r) * 80 + c4 * 4]);
        }
        CP_COMMIT();
    };

    stage(0, 0);
    for (int ch = 0; ch < 16; ch++) {
        const int buf = ch & 1;
        CP_WAIT0();
        __syncthreads();
        if (ch + 1 < 16) stage(ch + 1, buf ^ 1);
        if (active) {
            const float* sxa = smem + buf * BUF;
            const float* sxb = sxa + 2048;
            const float* sw  = sxb + 2048;
            #pragma unroll 8
            for (int cc = 0; cc < 32; cc++) {
                float2 av = *(const float2*)&sxa[cc * 64 + tt];
                float2 bv2 = *(const float2*)&sxb[cc * 64 + tt];
                float2 x0 = dup(fmaxf(av.x + bv2.x, 0.f));
                float2 x1 = dup(fmaxf(av.y + bv2.y, 0.f));
                const float2* wp = (const float2*)&sw[cc * 80 + cb];
                #pragma unroll
                for (int p = 0; p < 5; p++) {
                    float2 wd = wp[p];
                    acc[p][0] = ffma2(wd, x0, acc[p][0]);
                    acc[p][1] = ffma2(wd, x1, acc[p][1]);
                }
            }
        }
        __syncthreads();
    }
    if (active) {
        #pragma unroll
        for (int p = 0; p < 5; p++) {
            int co = cb + 2 * p;
            float2 bv = *(const float2*)&bias[co];
            float2 v0 = { acc[p][0].x + bv.x, acc[p][1].x + bv.x };
            float2 v1 = { acc[p][0].y + bv.y, acc[p][1].y + bv.y };
            *(float2*)&y[((size_t)(b * 80) + co    ) * 200 + t0 + tt] = v0;
            *(float2*)&y[((size_t)(b * 80) + co + 1) * 200 + t0 + tt] = v1;
        }
    }
}

__device__ __forceinline__ void qchain_body(
    const float* __restrict__ x, const float* __restrict__ w2T, const float* __restrict__ b2,
    const float* __restrict__ w3T, const float* __restrict__ b3,
    float* __restrict__ y, int b, int t_tile, float* smem)
{
    float* sx  = smem;          // 2048
    float* sw  = smem + 2048;   // 2560
    float* sh2 = smem + 4608;   // 5120
    const int tid = threadIdx.x;
    const int cg = tid & 7, tg = tid >> 3;
    const int tt = tg * 2, cb = cg * 10;
    const int t0 = t_tile * 64;
    const bool active = (t0 + tt) < 800;

    {   // phase 1
        float2 acc[5][2] = {};
        for (int ci0 = 0; ci0 < 160; ci0 += 32) {
            __syncthreads();
            for (int idx = tid; idx < 2048; idx += 256) {
                int cc = idx >> 6, j = idx & 63;
                int t = t0 + j;
                sx[idx] = (t < 800) ? x[((size_t)(b * 160) + ci0 + cc) * 800 + t] : 0.f;
            }
            for (int idx = tid; idx < 2560; idx += 256)
                sw[idx] = w2T[(size_t)ci0 * 80 + idx];
            __syncthreads();
            if (active) {
                #pragma unroll 8
                for (int cc = 0; cc < 32; cc++) {
                    float2 xq = *(const float2*)&sx[cc * 64 + tt];
                    float2 x0 = dup(xq.x), x1 = dup(xq.y);
                    const float2* wp = (const float2*)&sw[cc * 80 + cb];
                    #pragma unroll
                    for (int p = 0; p < 5; p++) {
                        float2 wd = wp[p];
                        acc[p][0] = ffma2(wd, x0, acc[p][0]);
                        acc[p][1] = ffma2(wd, x1, acc[p][1]);
                    }
                }
            }
        }
        if (active) {
            #pragma unroll
            for (int p = 0; p < 5; p++) {
                int co = cb + 2 * p;
                float2 bv = *(const float2*)&b2[co];
                float2 v0 = { fmaxf(acc[p][0].x + bv.x, 0.f), fmaxf(acc[p][1].x + bv.x, 0.f) };
                float2 v1 = { fmaxf(acc[p][0].y + bv.y, 0.f), fmaxf(acc[p][1].y + bv.y, 0.f) };
                *(float2*)&sh2[(co    ) * 64 + tt] = v0;
                *(float2*)&sh2[(co + 1) * 64 + tt] = v1;
            }
        }
    }
    {   // phase 2
        float2 acc[5][2] = {};
        for (int ci0 = 0; ci0 < 80; ci0 += 32) {
            const int CC = (80 - ci0 < 32) ? (80 - ci0) : 32;
            __syncthreads();
            for (int idx = tid; idx < CC * 80; idx += 256)
                sw[idx] = w3T[(size_t)ci0 * 80 + idx];
            __syncthreads();
            if (active) {
                #pragma unroll 8
                for (int cc = 0; cc < CC; cc++) {
                    float2 xq = *(const float2*)&sh2[(ci0 + cc) * 64 + tt];
                    float2 x0 = dup(xq.x), x1 = dup(xq.y);
                    const float2* wp = (const float2*)&sw[cc * 80 + cb];
                    #pragma unroll
                    for (int p = 0; p < 5; p++) {
                        float2 wd = wp[p];
                        acc[p][0] = ffma2(wd, x0, acc[p][0]);
                        acc[p][1] = ffma2(wd, x1, acc[p][1]);
                    }
                }
            }
        }
        if (active) {
            #pragma unroll
            for (int p = 0; p < 5; p++) {
                int co = cb + 2 * p;
                float2 bv = *(const float2*)&b3[co];
                float2 v0 = { acc[p][0].x + bv.x, acc[p][1].x + bv.x };
                float2 v1 = { acc[p][0].y + bv.y, acc[p][1].y + bv.y };
                *(float2*)&y[((size_t)(b * 80) + co    ) * 800 + t0 + tt] = v0;
                *(float2*)&y[((size_t)(b * 80) + co + 1) * 800 + t0 + tt] = v1;
            }
        }
    }
}

__global__ void stageB_kernel(
    const float* __restrict__ k1a, const float* __restrict__ k1b,
    const float* __restrict__ kb2, float* __restrict__ kout,
    const float* __restrict__ q1in, const float* __restrict__ qb2,
    const float* __restrict__ qb3, float* __restrict__ qout)
{
    extern __shared__ float smem[];
    int id = blockIdx.x;
    if (id < 64) key1x1_body(k1a, k1b, g_kw2T, kb2, kout, id >> 2, id & 3, smem);
    else {
        int j = id - 64;
        qchain_body(q1in, g_qw2T, qb2, g_qw3T, qb3, qout, j / 13, j % 13, smem);
    }
}

// =================== STAGE C: attention (R8 exact) ========================
__global__ void attention_kernel(const float* __restrict__ q, const float* __restrict__ k,
                                 const float* __restrict__ prior, float* __restrict__ out)
{
    extern __shared__ float smem[];
    float* sq = smem;              // 80*16
    float* sd = smem + 1280;       // 16*200

    const int b    = blockIdx.y;
    const int t1_0 = blockIdx.x * 16;
    const int tid  = threadIdx.x;

    {
        int i = tid;
        if (i < 320) {
            int c = i >> 2, jq = (i & 3) << 2;
            *(float4*)&sq[c * 16 + jq] =
                *(const float4*)&q[((size_t)(b * 80) + c) * 800 + t1_0 + jq];
        }
        i = tid + 256;
        if (i < 320) {
            int c = i >> 2, jq = (i & 3) << 2;
            *(float4*)&sq[c * 16 + jq] =
                *(const float4*)&q[((size_t)(b * 80) + c) * 800 + t1_0 + jq];
        }
    }
    __syncthreads();

    const int sg = tid & 63, jg = tid >> 6;
    if (sg < 50) {
        const int s0 = sg * 4, j0 = jg * 4;
        const float* kp = &k[(size_t)(b * 80) * 200 + s0];
        float2 acc[4][2] = {};
        float2 k2p[2] = {}, q2p[2] = {};

        float4 kbuf[4];
        #pragma unroll
        for (int i = 0; i < 4; i++) kbuf[i] = *(const float4*)(kp + i * 200);

        #pragma unroll
        for (int c0 = 0; c0 < 80; c0 += 4) {
            float4 cur[4];
            #pragma unroll
            for (int i = 0; i < 4; i++) cur[i] = kbuf[i];
            if (c0 + 4 < 80) {
                #pragma unroll
                for (int i = 0; i < 4; i++)
                    kbuf[i] = *(const float4*)(kp + (c0 + 4 + i) * 200);
            }
            #pragma unroll
            for (int i = 0; i < 4; i++) {
                int c = c0 + i;
                float4 kq = cur[i];
                float4 qa = *(const float4*)&sq[c * 16 + j0];
                float2 qp[2] = { {qa.x, qa.y}, {qa.z, qa.w} };
                float2 kpair0 = { kq.x, kq.y }, kpair1 = { kq.z, kq.w };
                k2p[0] = ffma2(kpair0, kpair0, k2p[0]);
                k2p[1] = ffma2(kpair1, kpair1, k2p[1]);
                q2p[0] = ffma2(qp[0], qp[0], q2p[0]);
                q2p[1] = ffma2(qp[1], qp[1], q2p[1]);
                float ks[4] = { kq.x, kq.y, kq.z, kq.w };
                #pragma unroll
                for (int si = 0; si < 4; si++) {
                    float2 kd = dup(ks[si]);
                    acc[si][0] = ffma2(kd, qp[0], acc[si][0]);
                    acc[si][1] = ffma2(kd, qp[1], acc[si][1]);
                }
            }
        }
        float k2s[4] = { k2p[0].x, k2p[0].y, k2p[1].x, k2p[1].y };
        float q2s[4] = { q2p[0].x, q2p[0].y, q2p[1].x, q2p[1].y };
        #pragma unroll
        for (int jj = 0; jj < 4; jj++) {
            int p = jj >> 1;
            float a0 = (jj & 1) ? acc[0][p].y : acc[0][p].x;
            float a1 = (jj & 1) ? acc[1][p].y : acc[1][p].x;
            float a2 = (jj & 1) ? acc[2][p].y : acc[2][p].x;
            float a3 = (jj & 1) ? acc[3][p].y : acc[3][p].x;
            float4 v = { -0.0005f * (q2s[jj] + k2s[0] - 2.f * a0),
                         -0.0005f * (q2s[jj] + k2s[1] - 2.f * a1),
                         -0.0005f * (q2s[jj] + k2s[2] - 2.f * a2),
                         -0.0005f * (q2s[jj] + k2s[3] - 2.f * a3) };
            *(float4*)&sd[(j0 + jj) * 200 + s0] = v;
        }
    }
    __syncthreads();

    const int warp = tid >> 5, lane = tid & 31;
    #pragma unroll
    for (int rr = 0; rr < 2; rr++) {
        int j = warp + rr * 8;
        const float* pr = &prior[((size_t)b * 800 + t1_0 + j) * 200];
        float prv[7];
        #pragma unroll
        for (int i = 0; i < 7; i++) {
            int s = lane + 32 * i;
            prv[i] = (s < 200) ? pr[s] : 1.f;
        }
        float m = -1e30f;
        #pragma unroll
        for (int i = 0; i < 7; i++) {
            int s = lane + 32 * i;
            if (s < 200) m = fmaxf(m, sd[j * 200 + s]);
        }
        #pragma unroll
        for (int o = 16; o; o >>= 1) m = fmaxf(m, __shfl_xor_sync(0xffffffffu, m, o));
        float sum = 0.f;
        #pragma unroll
        for (int i = 0; i < 7; i++) {
            int s = lane + 32 * i;
            if (s < 200) sum += __expf(sd[j * 200 + s] - m);
        }
        #pragma unroll
        for (int o = 16; o; o >>= 1) sum += __shfl_xor_sync(0xffffffffu, sum, o);
        float lse = m + __logf(sum);
        float* op = &out[((size_t)b * 800 + t1_0 + j) * 200];
        #pragma unroll
        for (int i = 0; i < 7; i++) {
            int s = lane + 32 * i;
            if (s < 200) op[s] = sd[j * 200 + s] - lse + __logf(prv[i] + 1e-8f);
        }
    }
}

// -------------------------------- launch ---------------------------------
extern "C" void kernel_launch(void* const* d_in, const int* in_sizes, int n_in,
                              void* d_out, int out_size)
{
    const float* queries = (const float*)d_in[0];
    const float* keys    = (const float*)d_in[1];
    const float* prior   = (const float*)d_in[2];
    const float* kw1 = (const float*)d_in[3];
    const float* kb1 = (const float*)d_in[4];
    const float* kw2 = (const float*)d_in[5];
    const float* kb2 = (const float*)d_in[6];
    const float* qw1 = (const float*)d_in[7];
    const float* qb1 = (const float*)d_in[8];
    const float* qw2 = (const float*)d_in[9];
    const float* qb2 = (const float*)d_in[10];
    const float* qw3 = (const float*)d_in[11];
    const float* qb3 = (const float*)d_in[12];
    float* out = (float*)d_out;

    float *k1buf, *k1bufb, *kbuf, *q1buf, *qbuf;
    float *kw1T, *qw1T, *kw2T, *qw2T, *qw3T;
    cudaGetSymbolAddress((void**)&k1buf,  g_k1);
    cudaGetSymbolAddress((void**)&k1bufb, g_k1b);
    cudaGetSymbolAddress((void**)&kbuf,   g_k);
    cudaGetSymbolAddress((void**)&q1buf,  g_q1);
    cudaGetSymbolAddress((void**)&qbuf,   g_qf);
    cudaGetSymbolAddress((void**)&kw1T, g_kw1T);
    cudaGetSymbolAddress((void**)&qw1T, g_qw1T);
    cudaGetSymbolAddress((void**)&kw2T, g_kw2T);
    cudaGetSymbolAddress((void**)&qw2T, g_qw2T);
    cudaGetSymbolAddress((void**)&qw3T, g_qw3T);

    const int smem_A    = 2 * (8 * 68 + 24 * 160) * 4;           // 35072 (query max)
    const int smem_B    = 2 * 6656 * 4;                          // 53248 (key1x1 max)
    const int smem_attn = (1280 + 16 * 200) * 4;                 // 17920

    cudaFuncSetAttribute((const void*)stageA_kernel,
                         cudaFuncAttributeMaxDynamicSharedMemorySize, smem_A);
    cudaFuncSetAttribute((const void*)stageB_kernel,
                         cudaFuncAttributeMaxDynamicSharedMemorySize, smem_B);

    prep_kernel<<<496, 256>>>(kw1, qw1, kw2, qw2, qw3, kw1T, qw1T, kw2T, qw2T, qw3T);
    stageA_kernel<<<1232, 256, smem_A>>>(keys, kb1, queries, qb1, k1buf, k1bufb, q1buf);
    stageB_kernel<<<272, 256, smem_B>>>(k1buf, k1bufb, kb2, kbuf, q1buf, qb2, qb3, qbuf);
    attention_kernel<<<dim3(50, 16), 256, smem_attn>>>(qbuf, kbuf, prior, out);
}

// round 16
// speedup vs baseline: 1.0027x; 1.0027x over previous
#include <cuda_runtime.h>
#include <cstdint>
#include <math.h>

// ---------------- scratch (device globals; no allocation) ----------------
__device__ float g_k1  [16 * 512 * 200];   // key conv1 out
__device__ float g_k   [16 *  80 * 200];   // key encoder out
__device__ float g_q1  [16 * 160 * 800];   // query conv1 out
__device__ float g_qf  [16 *  80 * 800];   // query encoder out
__device__ float g_kw1T[768 * 512];        // kw1 transposed [(ci*3+k)][co]
__device__ float g_qw1T[240 * 160];
__device__ float g_kw2T[512 *  80];        // kw2 transposed [ci][co]
__device__ float g_qw2T[160 *  80];
__device__ float g_qw3T[ 80 *  80];

// ---------------- packed fp32x2 FMA (Blackwell) ---------------------------
__device__ __forceinline__ float2 ffma2(float2 a, float2 b, float2 c) {
    unsigned long long ua = *reinterpret_cast<unsigned long long*>(&a);
    unsigned long long ub = *reinterpret_cast<unsigned long long*>(&b);
    unsigned long long uc = *reinterpret_cast<unsigned long long*>(&c);
    unsigned long long ud;
    asm("fma.rn.f32x2 %0, %1, %2, %3;" : "=l"(ud) : "l"(ua), "l"(ub), "l"(uc));
    return *reinterpret_cast<float2*>(&ud);
}
__device__ __forceinline__ float2 dup(float v) { return make_float2(v, v); }

// ---------------- cp.async helpers ----------------------------------------
__device__ __forceinline__ void cp_async4(void* dst, const void* src, bool pred) {
    unsigned int d = (unsigned int)__cvta_generic_to_shared(dst);
    int sz = pred ? 4 : 0;
    asm volatile("cp.async.ca.shared.global [%0], [%1], 4, %2;"
                 :: "r"(d), "l"(src), "r"(sz) : "memory");
}
__device__ __forceinline__ void cp_async16(void* dst, const void* src) {
    unsigned int d = (unsigned int)__cvta_generic_to_shared(dst);
    asm volatile("cp.async.ca.shared.global [%0], [%1], 16;"
                 :: "r"(d), "l"(src) : "memory");
}
#define CP_COMMIT() asm volatile("cp.async.commit_group;" ::: "memory")
#define CP_WAIT0()  asm volatile("cp.async.wait_group 0;" ::: "memory")

// =================== PREP: tiled (coalesced) weight transposes ============
__global__ void prep_kernel(const float* __restrict__ kw1, const float* __restrict__ qw1,
                            const float* __restrict__ kw2, const float* __restrict__ qw2,
                            const float* __restrict__ qw3,
                            float* __restrict__ kw1T, float* __restrict__ qw1T,
                            float* __restrict__ kw2T, float* __restrict__ qw2T,
                            float* __restrict__ qw3T)
{
    __shared__ float tile[32][33];
    int id = blockIdx.x;
    const float* src; float* dst; int R, C, bi, bj;
    if (id < 384)            { src = kw1; dst = kw1T; R = 512; C = 768; bi = id / 24; bj = id % 24; }
    else if ((id -= 384) < 40) { src = qw1; dst = qw1T; R = 160; C = 240; bi = id / 8;  bj = id % 8;  }
    else if ((id -= 40) < 48)  { src = kw2; dst = kw2T; R = 80;  C = 512; bi = id / 16; bj = id % 16; }
    else if ((id -= 48) < 15)  { src = qw2; dst = qw2T; R = 80;  C = 160; bi = id / 5;  bj = id % 5;  }
    else      { id -= 15;        src = qw3; dst = qw3T; R = 80;  C = 80;  bi = id / 3;  bj = id % 3;  }

    const int r0 = bi * 32, c0 = bj * 32;
    const int tx = threadIdx.x & 31, ty = threadIdx.x >> 5;

    #pragma unroll
    for (int yy = ty; yy < 32; yy += 8) {
        int r = r0 + yy, c = c0 + tx;
        tile[yy][tx] = (r < R && c < C) ? src[(size_t)r * C + c] : 0.f;
    }
    __syncthreads();
    #pragma unroll
    for (int yy = ty; yy < 32; yy += 8) {
        int c = c0 + yy, r = r0 + tx;
        if (c < C && r < R) dst[(size_t)c * R + r] = tile[tx][yy];
    }
}

// =================== STAGE A: conv3 with cp.async double buffering ========
// runtime (t0, W): block covers t in [t0, t0+W), W multiple of 4, <= 64.
template<int CIN, int COUT, int TLEN, int CPAIRS, int CICH>
__device__ __forceinline__ void conv3_body(
    const float* __restrict__ x, const float* __restrict__ wT,
    const float* __restrict__ bias, float* __restrict__ y,
    int b, int t0, int W, int co_tile, float* smem)
{
    constexpr int COT = 32 * CPAIRS;
    constexpr int NW4 = CICH * 3 * COT / 4;
    constexpr int BUF = CICH * 68 + CICH * 3 * COT;
    constexpr int NCH = CIN / CICH;

    const int tid = threadIdx.x;
    const int cg = tid & 15, tg = tid >> 4;
    const int tt = tg * 4, ct = cg * 2 * CPAIRS;
    const int co0 = co_tile * COT;
    const bool active = (tt < W) && (t0 + tt) < TLEN;
    const int NX = CICH * (W + 2);

    auto stage = [&](int ch, int buf) {
        float* sx = smem + buf * BUF;
        float* sw = sx + CICH * 68;
        const int ci0 = ch * CICH;
        for (int idx = tid; idx < NX; idx += 256) {
            int cc = idx / (W + 2), j = idx - cc * (W + 2);
            int t = t0 + j - 1;
            bool p = (t >= 0 && t < TLEN);
            cp_async4(&sx[cc * 68 + j],
                      &x[((size_t)(b * CIN) + ci0 + cc) * TLEN + t], p);
        }
        for (int idx = tid; idx < NW4; idx += 256) {
            int r = idx / (COT / 4), c4 = idx - r * (COT / 4);
            cp_async16(&sw[r * COT + c4 * 4],
                       &wT[(size_t)(ci0 * 3 + r) * COUT + co0 + c4 * 4]);
        }
        CP_COMMIT();
    };

    float2 acc[CPAIRS][4] = {};

    stage(0, 0);
    for (int ch = 0; ch < NCH; ch++) {
        const int buf = ch & 1;
        CP_WAIT0();
        __syncthreads();
        if (ch + 1 < NCH) stage(ch + 1, buf ^ 1);

        if (active) {
            const float* sx = smem + buf * BUF;
            const float* sw = sx + CICH * 68;
            #pragma unroll
            for (int cc = 0; cc < CICH; cc++) {
                const float* xr = &sx[cc * 68 + tt];
                float4 xa = *(const float4*)xr;
                float2 xb = *(const float2*)(xr + 4);
                float2 xv[6] = { dup(xa.x), dup(xa.y), dup(xa.z),
                                 dup(xa.w), dup(xb.x), dup(xb.y) };
                float2 wk[3][CPAIRS];
                #pragma unroll
                for (int k = 0; k < 3; k++) {
                    const float* wb = &sw[(cc * 3 + k) * COT + ct];
                    if constexpr ((CPAIRS & 1) == 0) {
                        #pragma unroll
                        for (int q = 0; q < CPAIRS / 2; q++) {
                            float4 wv = *(const float4*)(wb + 4 * q);
                            wk[k][2*q]   = make_float2(wv.x, wv.y);
                            wk[k][2*q+1] = make_float2(wv.z, wv.w);
                        }
                    } else {
                        #pragma unroll
                        for (int p = 0; p < CPAIRS; p++)
                            wk[k][p] = *(const float2*)(wb + 2 * p);
                    }
                }
                #pragma unroll
                for (int u = 0; u < 4; u++)
                    #pragma unroll
                    for (int p = 0; p < CPAIRS; p++)
                        acc[p][u] = ffma2(wk[0][p], xv[u],
                                    ffma2(wk[1][p], xv[u+1],
                                    ffma2(wk[2][p], xv[u+2], acc[p][u])));
            }
        }
        __syncthreads();
    }

    if (active) {
        #pragma unroll
        for (int p = 0; p < CPAIRS; p++) {
            int co = co0 + ct + 2 * p;
            float2 bv = *(const float2*)&bias[co];
            float4 v0 = { fmaxf(acc[p][0].x + bv.x, 0.f), fmaxf(acc[p][1].x + bv.x, 0.f),
                          fmaxf(acc[p][2].x + bv.x, 0.f), fmaxf(acc[p][3].x + bv.x, 0.f) };
            float4 v1 = { fmaxf(acc[p][0].y + bv.y, 0.f), fmaxf(acc[p][1].y + bv.y, 0.f),
                          fmaxf(acc[p][2].y + bv.y, 0.f), fmaxf(acc[p][3].y + bv.y, 0.f) };
            *(float4*)&y[((size_t)(b * COUT) + co    ) * TLEN + t0 + tt] = v0;
            *(float4*)&y[((size_t)(b * COUT) + co + 1) * TLEN + t0 + tt] = v1;
        }
    }
}

__global__ void __launch_bounds__(256)
stageA_kernel(
    const float* __restrict__ keys, const float* __restrict__ kb1,
    const float* __restrict__ queries, const float* __restrict__ qb1,
    float* __restrict__ k1out, float* __restrict__ q1out)
{
    extern __shared__ float smem[];
    int id = blockIdx.x;
    if (id < 512) {                      // key: balanced t-tiles 52/52/48/48
        int b = id >> 5, r = id & 31;
        int tt4 = r & 3;
        int t0 = (tt4 == 0) ? 0 : (tt4 == 1) ? 52 : (tt4 == 2) ? 104 : 152;
        int W  = (tt4 < 2) ? 52 : 48;
        conv3_body<256, 512, 200, 2, 16>(keys, g_kw1T, kb1, k1out,
                                         b, t0, W, r >> 2, smem);
    } else {                             // query: 13 tiles of 64
        int j = id - 512;
        conv3_body<80, 160, 800, 5, 8>(queries, g_qw1T, qb1, q1out,
                                       j / 13, (j % 13) * 64, 64, 0, smem);
    }
}

// =================== STAGE B: key 1x1 (cp.async piped) + qchain ===========
__device__ __forceinline__ void key1x1_body(
    const float* __restrict__ x, const float* __restrict__ wT,
    const float* __restrict__ bias, float* __restrict__ y,
    int b, int t_tile, float* smem)
{
    constexpr int BUF = 2048 + 2560;
    const int tid = threadIdx.x;
    const int cg = tid & 7, tg = tid >> 3;
    const int tt = tg * 2, cb = cg * 10;
    const int t0 = t_tile * 64;
    const bool active = (t0 + tt) < 200;
    float2 acc[5][2] = {};

    auto stage = [&](int ch, int buf) {
        float* sx = smem + buf * BUF;
        float* sw = sx + 2048;
        const int ci0 = ch * 32;
        for (int idx = tid; idx < 2048; idx += 256) {
            int cc = idx >> 6, j = idx & 63;
            int t = t0 + j;
            cp_async4(&sx[idx], &x[((size_t)(b * 512) + ci0 + cc) * 200 + t],
                      t < 200);
        }
        for (int idx = tid; idx < 640; idx += 256) {
            int r = idx / 20, c4 = idx - r * 20;
            cp_async16(&sw[r * 80 + c4 * 4],
                       &wT[(size_t)(ci0 + r) * 80 + c4 * 4]);
        }
        CP_COMMIT();
    };

    stage(0, 0);
    for (int ch = 0; ch < 16; ch++) {
        const int buf = ch & 1;
        CP_WAIT0();
        __syncthreads();
        if (ch + 1 < 16) stage(ch + 1, buf ^ 1);
        if (active) {
            const float* sx = smem + buf * BUF;
            const float* sw = sx + 2048;
            #pragma unroll 8
            for (int cc = 0; cc < 32; cc++) {
                float2 xq = *(const float2*)&sx[cc * 64 + tt];
                float2 x0 = dup(xq.x), x1 = dup(xq.y);
                const float2* wp = (const float2*)&sw[cc * 80 + cb];
                #pragma unroll
                for (int p = 0; p < 5; p++) {
                    float2 wd = wp[p];
                    acc[p][0] = ffma2(wd, x0, acc[p][0]);
                    acc[p][1] = ffma2(wd, x1, acc[p][1]);
                }
            }
        }
        __syncthreads();
    }
    if (active) {
        #pragma unroll
        for (int p = 0; p < 5; p++) {
            int co = cb + 2 * p;
            float2 bv = *(const float2*)&bias[co];
            float2 v0 = { acc[p][0].x + bv.x, acc[p][1].x + bv.x };
            float2 v1 = { acc[p][0].y + bv.y, acc[p][1].y + bv.y };
            *(float2*)&y[((size_t)(b * 80) + co    ) * 200 + t0 + tt] = v0;
            *(float2*)&y[((size_t)(b * 80) + co + 1) * 200 + t0 + tt] = v1;
        }
    }
}

__device__ __forceinline__ void qchain_body(
    const float* __restrict__ x, const float* __restrict__ w2T, const float* __restrict__ b2,
    const float* __restrict__ w3T, const float* __restrict__ b3,
    float* __restrict__ y, int b, int t_tile, float* smem)
{
    float* sx  = smem;          // 2048
    float* sw  = smem + 2048;   // 2560
    float* sh2 = smem + 4608;   // 5120
    const int tid = threadIdx.x;
    const int cg = tid & 7, tg = tid >> 3;
    const int tt = tg * 2, cb = cg * 10;
    const int t0 = t_tile * 64;
    const bool active = (t0 + tt) < 800;

    {   // phase 1
        float2 acc[5][2] = {};
        for (int ci0 = 0; ci0 < 160; ci0 += 32) {
            __syncthreads();
            for (int idx = tid; idx < 2048; idx += 256) {
                int cc = idx >> 6, j = idx & 63;
                int t = t0 + j;
                sx[idx] = (t < 800) ? x[((size_t)(b * 160) + ci0 + cc) * 800 + t] : 0.f;
            }
            for (int idx = tid; idx < 2560; idx += 256)
                sw[idx] = w2T[(size_t)ci0 * 80 + idx];
            __syncthreads();
            if (active) {
                #pragma unroll 8
                for (int cc = 0; cc < 32; cc++) {
                    float2 xq = *(const float2*)&sx[cc * 64 + tt];
                    float2 x0 = dup(xq.x), x1 = dup(xq.y);
                    const float2* wp = (const float2*)&sw[cc * 80 + cb];
                    #pragma unroll
                    for (int p = 0; p < 5; p++) {
                        float2 wd = wp[p];
                        acc[p][0] = ffma2(wd, x0, acc[p][0]);
                        acc[p][1] = ffma2(wd, x1, acc[p][1]);
                    }
                }
            }
        }
        if (active) {
            #pragma unroll
            for (int p = 0; p < 5; p++) {
                int co = cb + 2 * p;
                float2 bv = *(const float2*)&b2[co];
                float2 v0 = { fmaxf(acc[p][0].x + bv.x, 0.f), fmaxf(acc[p][1].x + bv.x, 0.f) };
                float2 v1 = { fmaxf(acc[p][0].y + bv.y, 0.f), fmaxf(acc[p][1].y + bv.y, 0.f) };
                *(float2*)&sh2[(co    ) * 64 + tt] = v0;
                *(float2*)&sh2[(co + 1) * 64 + tt] = v1;
            }
        }
    }
    {   // phase 2
        float2 acc[5][2] = {};
        for (int ci0 = 0; ci0 < 80; ci0 += 32) {
            const int CC = (80 - ci0 < 32) ? (80 - ci0) : 32;
            __syncthreads();
            for (int idx = tid; idx < CC * 80; idx += 256)
                sw[idx] = w3T[(size_t)ci0 * 80 + idx];
            __syncthreads();
            if (active) {
                #pragma unroll 8
                for (int cc = 0; cc < CC; cc++) {
                    float2 xq = *(const float2*)&sh2[(ci0 + cc) * 64 + tt];
                    float2 x0 = dup(xq.x), x1 = dup(xq.y);
                    const float2* wp = (const float2*)&sw[cc * 80 + cb];
                    #pragma unroll
                    for (int p = 0; p < 5; p++) {
                        float2 wd = wp[p];
                        acc[p][0] = ffma2(wd, x0, acc[p][0]);
                        acc[p][1] = ffma2(wd, x1, acc[p][1]);
                    }
                }
            }
        }
        if (active) {
            #pragma unroll
            for (int p = 0; p < 5; p++) {
                int co = cb + 2 * p;
                float2 bv = *(const float2*)&b3[co];
                float2 v0 = { acc[p][0].x + bv.x, acc[p][1].x + bv.x };
                float2 v1 = { acc[p][0].y + bv.y, acc[p][1].y + bv.y };
                *(float2*)&y[((size_t)(b * 80) + co    ) * 800 + t0 + tt] = v0;
                *(float2*)&y[((size_t)(b * 80) + co + 1) * 800 + t0 + tt] = v1;
            }
        }
    }
}

__global__ void stageB_kernel(
    const float* __restrict__ k1in, const float* __restrict__ kb2, float* __restrict__ kout,
    const float* __restrict__ q1in, const float* __restrict__ qb2,
    const float* __restrict__ qb3, float* __restrict__ qout)
{
    extern __shared__ float smem[];
    int id = blockIdx.x;
    if (id < 64) key1x1_body(k1in, g_kw2T, kb2, kout, id >> 2, id & 3, smem);
    else {
        int j = id - 64;
        qchain_body(q1in, g_qw2T, qb2, g_qw3T, qb3, qout, j / 13, j % 13, smem);
    }
}

// =================== STAGE C: attention (R8 exact) ========================
__global__ void attention_kernel(const float* __restrict__ q, const float* __restrict__ k,
                                 const float* __restrict__ prior, float* __restrict__ out)
{
    extern __shared__ float smem[];
    float* sq = smem;              // 80*16
    float* sd = smem + 1280;       // 16*200

    const int b    = blockIdx.y;
    const int t1_0 = blockIdx.x * 16;
    const int tid  = threadIdx.x;

    {
        int i = tid;
        if (i < 320) {
            int c = i >> 2, jq = (i & 3) << 2;
            *(float4*)&sq[c * 16 + jq] =
                *(const float4*)&q[((size_t)(b * 80) + c) * 800 + t1_0 + jq];
        }
        i = tid + 256;
        if (i < 320) {
            int c = i >> 2, jq = (i & 3) << 2;
            *(float4*)&sq[c * 16 + jq] =
                *(const float4*)&q[((size_t)(b * 80) + c) * 800 + t1_0 + jq];
        }
    }
    __syncthreads();

    const int sg = tid & 63, jg = tid >> 6;
    if (sg < 50) {
        const int s0 = sg * 4, j0 = jg * 4;
        const float* kp = &k[(size_t)(b * 80) * 200 + s0];
        float2 acc[4][2] = {};
        float2 k2p[2] = {}, q2p[2] = {};

        float4 kbuf[4];
        #pragma unroll
        for (int i = 0; i < 4; i++) kbuf[i] = *(const float4*)(kp + i * 200);

        #pragma unroll
        for (int c0 = 0; c0 < 80; c0 += 4) {
            float4 cur[4];
            #pragma unroll
            for (int i = 0; i < 4; i++) cur[i] = kbuf[i];
            if (c0 + 4 < 80) {
                #pragma unroll
                for (int i = 0; i < 4; i++)
                    kbuf[i] = *(const float4*)(kp + (c0 + 4 + i) * 200);
            }
            #pragma unroll
            for (int i = 0; i < 4; i++) {
                int c = c0 + i;
                float4 kq = cur[i];
                float4 qa = *(const float4*)&sq[c * 16 + j0];
                float2 qp[2] = { {qa.x, qa.y}, {qa.z, qa.w} };
                float2 kpair0 = { kq.x, kq.y }, kpair1 = { kq.z, kq.w };
                k2p[0] = ffma2(kpair0, kpair0, k2p[0]);
                k2p[1] = ffma2(kpair1, kpair1, k2p[1]);
                q2p[0] = ffma2(qp[0], qp[0], q2p[0]);
                q2p[1] = ffma2(qp[1], qp[1], q2p[1]);
                float ks[4] = { kq.x, kq.y, kq.z, kq.w };
                #pragma unroll
                for (int si = 0; si < 4; si++) {
                    float2 kd = dup(ks[si]);
                    acc[si][0] = ffma2(kd, qp[0], acc[si][0]);
                    acc[si][1] = ffma2(kd, qp[1], acc[si][1]);
                }
            }
        }
        float k2s[4] = { k2p[0].x, k2p[0].y, k2p[1].x, k2p[1].y };
        float q2s[4] = { q2p[0].x, q2p[0].y, q2p[1].x, q2p[1].y };
        #pragma unroll
        for (int jj = 0; jj < 4; jj++) {
            int p = jj >> 1;
            float a0 = (jj & 1) ? acc[0][p].y : acc[0][p].x;
            float a1 = (jj & 1) ? acc[1][p].y : acc[1][p].x;
            float a2 = (jj & 1) ? acc[2][p].y : acc[2][p].x;
            float a3 = (jj & 1) ? acc[3][p].y : acc[3][p].x;
            float4 v = { -0.0005f * (q2s[jj] + k2s[0] - 2.f * a0),
                         -0.0005f * (q2s[jj] + k2s[1] - 2.f * a1),
                         -0.0005f * (q2s[jj] + k2s[2] - 2.f * a2),
                         -0.0005f * (q2s[jj] + k2s[3] - 2.f * a3) };
            *(float4*)&sd[(j0 + jj) * 200 + s0] = v;
        }
    }
    __syncthreads();

    const int warp = tid >> 5, lane = tid & 31;
    #pragma unroll
    for (int rr = 0; rr < 2; rr++) {
        int j = warp + rr * 8;
        const float* pr = &prior[((size_t)b * 800 + t1_0 + j) * 200];
        float prv[7];
        #pragma unroll
        for (int i = 0; i < 7; i++) {
            int s = lane + 32 * i;
            prv[i] = (s < 200) ? pr[s] : 1.f;
        }
        float m = -1e30f;
        #pragma unroll
        for (int i = 0; i < 7; i++) {
            int s = lane + 32 * i;
            if (s < 200) m = fmaxf(m, sd[j * 200 + s]);
        }
        #pragma unroll
        for (int o = 16; o; o >>= 1) m = fmaxf(m, __shfl_xor_sync(0xffffffffu, m, o));
        float sum = 0.f;
        #pragma unroll
        for (int i = 0; i < 7; i++) {
            int s = lane + 32 * i;
            if (s < 200) sum += __expf(sd[j * 200 + s] - m);
        }
        #pragma unroll
        for (int o = 16; o; o >>= 1) sum += __shfl_xor_sync(0xffffffffu, sum, o);
        float lse = m + __logf(sum);
        float* op = &out[((size_t)b * 800 + t1_0 + j) * 200];
        #pragma unroll
        for (int i = 0; i < 7; i++) {
            int s = lane + 32 * i;
            if (s < 200) op[s] = sd[j * 200 + s] - lse + __logf(prv[i] + 1e-8f);
        }
    }
}

// -------------------------------- launch ---------------------------------
extern "C" void kernel_launch(void* const* d_in, const int* in_sizes, int n_in,
                              void* d_out, int out_size)
{
    const float* queries = (const float*)d_in[0];
    const float* keys    = (const float*)d_in[1];
    const float* prior   = (const float*)d_in[2];
    const float* kw1 = (const float*)d_in[3];
    const float* kb1 = (const float*)d_in[4];
    const float* kw2 = (const float*)d_in[5];
    const float* kb2 = (const float*)d_in[6];
    const float* qw1 = (const float*)d_in[7];
    const float* qb1 = (const float*)d_in[8];
    const float* qw2 = (const float*)d_in[9];
    const float* qb2 = (const float*)d_in[10];
    const float* qw3 = (const float*)d_in[11];
    const float* qb3 = (const float*)d_in[12];
    float* out = (float*)d_out;

    float *k1buf, *kbuf, *q1buf, *qbuf;
    float *kw1T, *qw1T, *kw2T, *qw2T, *qw3T;
    cudaGetSymbolAddress((void**)&k1buf, g_k1);
    cudaGetSymbolAddress((void**)&kbuf,  g_k);
    cudaGetSymbolAddress((void**)&q1buf, g_q1);
    cudaGetSymbolAddress((void**)&qbuf,  g_qf);
    cudaGetSymbolAddress((void**)&kw1T, g_kw1T);
    cudaGetSymbolAddress((void**)&qw1T, g_qw1T);
    cudaGetSymbolAddress((void**)&kw2T, g_kw2T);
    cudaGetSymbolAddress((void**)&qw2T, g_qw2T);
    cudaGetSymbolAddress((void**)&qw3T, g_qw3T);

    const int smem_A    = 2 * (8 * 68 + 24 * 160) * 4;           // 35072 (query max)
    const int smem_B    = 9728 * 4;                              // 38912 (qchain max)
    const int smem_attn = (1280 + 16 * 200) * 4;                 // 17920

    cudaFuncSetAttribute((const void*)stageA_kernel,
                         cudaFuncAttributeMaxDynamicSharedMemorySize, smem_A);
    cudaFuncSetAttribute((const void*)stageB_kernel,
                         cudaFuncAttributeMaxDynamicSharedMemorySize, smem_B);

    prep_kernel<<<496, 256>>>(kw1, qw1, kw2, qw2, qw3, kw1T, qw1T, kw2T, qw2T, qw3T);
    stageA_kernel<<<720, 256, smem_A>>>(keys, kb1, queries, qb1, k1buf, q1buf);
    stageB_kernel<<<272, 256, smem_B>>>(k1buf, kb2, kbuf, q1buf, qb2, qb3, qbuf);
    attention_kernel<<<dim3(50, 16), 256, smem_attn>>>(qbuf, kbuf, prior, out);
}